// round 14
// baseline (speedup 1.0000x reference)
#include <cuda_runtime.h>
#include <cuda_bf16.h>
#include <cuda_fp16.h>
#include <cstdint>
#include <math.h>

#define NB 8
#define CC 256
#define NPIX 1024
#define HEADS 8
#define HD 128
#define MQKV 3072
#define DIM 1024

// Hamilton tables
__constant__ int   c_IDX[16] = {0,1,2,3, 1,0,3,2, 2,3,0,1, 3,2,1,0};
__constant__ float c_SGN[16] = {1.f,-1.f,-1.f,-1.f, 1.f,1.f,1.f,-1.f,
                                1.f,-1.f,1.f,1.f, 1.f,1.f,-1.f,1.f};

// Scratch (device globals). ALL tensor-core operands pre-tiled + pre-swizzled
// (fp16), fetched with single cp.async.bulk copies.
__device__ __half g_WeffH[(size_t)MQKV*DIM];
__device__ __half g_WprojH[(size_t)DIM*DIM];
__device__ __half g_XTH[(size_t)NB*NPIX*DIM];
__device__ __half g_OTH[(size_t)NB*NPIX*DIM];
__device__ __half g_QTH[(size_t)NB*HEADS*NPIX*HD];  // scale*log2e folded
__device__ __half g_KTH[(size_t)NB*HEADS*NPIX*HD];
__device__ __half g_VH[(size_t)NB*HEADS*HD*NPIX];

// ===========================================================================
// Helpers
// ===========================================================================
__device__ __forceinline__ uint32_t smem_u32(const void* p){
  uint32_t a;
  asm("{ .reg .u64 t; cvta.to.shared.u64 t, %1; cvt.u32.u64 %0, t; }"
      : "=r"(a) : "l"(p));
  return a;
}
__device__ __forceinline__ void ldm4(uint32_t r[4], uint32_t addr){
  asm volatile("ldmatrix.sync.aligned.m8n8.x4.shared.b16 {%0,%1,%2,%3}, [%4];"
    : "=r"(r[0]),"=r"(r[1]),"=r"(r[2]),"=r"(r[3]) : "r"(addr));
}
__device__ __forceinline__ void mma16816h(float c[4], const uint32_t a[4],
                                          const uint32_t b[2]){
  asm volatile(
    "mma.sync.aligned.m16n8k16.row.col.f32.f16.f16.f32 "
    "{%0,%1,%2,%3}, {%4,%5,%6,%7}, {%8,%9}, {%0,%1,%2,%3};"
    : "+f"(c[0]),"+f"(c[1]),"+f"(c[2]),"+f"(c[3])
    : "r"(a[0]),"r"(a[1]),"r"(a[2]),"r"(a[3]), "r"(b[0]),"r"(b[1]));
}
__device__ __forceinline__ uint32_t pkhf2(float a, float b){
  __half2 t = __floats2half2_rn(a, b);
  return *(uint32_t*)&t;
}
#define BULKCP(dst, src, bytes, mb) \
  asm volatile("cp.async.bulk.shared::cluster.global.mbarrier::complete_tx::bytes [%0], [%1], %2, [%3];" \
    :: "r"((uint32_t)(dst)), "l"(src), "r"((uint32_t)(bytes)), "r"((uint32_t)(mb)) : "memory")
#define MBARRIER_INIT(mb, c) \
  asm volatile("mbarrier.init.shared.b64 [%0], %1;" :: "r"((uint32_t)(mb)), "r"((uint32_t)(c)) : "memory")
#define MBARRIER_EXPECT_TX(mb, tx) \
  asm volatile("mbarrier.arrive.expect_tx.shared.b64 _, [%0], %1;" :: "r"((uint32_t)(mb)), "r"((uint32_t)(tx)) : "memory")
#define MBARRIER_WAIT_PARITY(mb, ph) do { \
    uint32_t _m = (uint32_t)(mb); uint32_t _p = (uint32_t)(ph); uint32_t _d; \
    asm volatile("{\n\t.reg .pred p;\n\t" \
        "mbarrier.try_wait.parity.acquire.cta.shared::cta.b64 p, [%1], %2;\n\t" \
        "selp.b32 %0, 1, 0, p;\n\t}" : "=r"(_d) : "r"(_m), "r"(_p) : "memory"); \
    if (!_d) { \
      asm volatile("{\n\t.reg .pred P1;\n\t" \
        "WL_%=:\n\t" \
        "mbarrier.try_wait.parity.acquire.cta.shared::cta.b64 P1, [%0], %1, 0x989680;\n\t" \
        "@P1 bra.uni WD_%=;\n\t" \
        "bra.uni WL_%=;\n\t" \
        "WD_%=:\n\t}" :: "r"(_m), "r"(_p) : "memory"); \
    } \
  } while(0)

// swizzled byte offsets inside tiles (row-major rows of 64/128/256 bytes)
__device__ __forceinline__ uint32_t swz64 (uint32_t r, uint32_t c16){ return r*64u  + ((c16 ^ ((r>>1)&3u))<<4); }
__device__ __forceinline__ uint32_t swz128(uint32_t r, uint32_t c16){ return r*128u + ((c16 ^ (r&7u))<<4); }
__device__ __forceinline__ uint32_t swz256(uint32_t r, uint32_t c16){ return r*256u + ((c16 ^ (r&7u))<<4); }

// ===========================================================================
// Prep: Hamilton-folded weights -> fp16, tiled+swizzled
// ===========================================================================
__global__ void prep_w_kernel(const float* __restrict__ w,
                              char* __restrict__ outH, int is_qkv){
  int idx = blockIdx.x*256 + threadIdx.x;
  int g = idx >> 7, c = idx & 127;
  int k0 = c*8;
  int qc, o;
  if (is_qkv){ qc = g / 768; o = g - qc*768; } else { qc = g >> 8; o = g & 255; }
  int p = k0 >> 8, cch = k0 & 255;
  float s = c_SGN[qc*4+p];
  const float* src = w + ((size_t)(c_IDX[qc*4+p]*(is_qkv?768:256) + o))*256 + cch;
  float4 v0 = *(const float4*)src;
  float4 v1 = *(const float4*)(src+4);
  size_t base = ((size_t)((g>>8)*32 + (c>>2)))*16384;
  uint32_t off = swz64(g & 255, c & 3);
  uint4 H;
  H.x = pkhf2(v0.x*s, v0.y*s); H.y = pkhf2(v0.z*s, v0.w*s);
  H.z = pkhf2(v1.x*s, v1.y*s); H.w = pkhf2(v1.z*s, v1.w*s);
  *(uint4*)(outH + base + off) = H;
}

// x (b, cch, p, n) fp32 -> XT tiles (b, ntile, kt) fp16
__global__ void prep_xt_kernel(const float* __restrict__ x){
  __shared__ float sm[32][33];
  int b = blockIdx.z, k0 = blockIdx.x*32, n0 = blockIdx.y*32;
  int t = threadIdx.x;
  {
    int kk = t >> 3, n4 = (t & 7) << 2;
    int k = k0 + kk; int p = k >> 8, cch = k & 255;
    float4 v = *(const float4*)&x[((size_t)((b*CC+cch)*4 + p))*NPIX + n0 + n4];
    sm[kk][n4] = v.x; sm[kk][n4+1] = v.y; sm[kk][n4+2] = v.z; sm[kk][n4+3] = v.w;
  }
  __syncthreads();
  {
    int nn = t >> 3, k4 = (t & 7) << 2;
    int n = n0 + nn;
    uint2 hp = make_uint2(pkhf2(sm[k4+0][nn], sm[k4+1][nn]),
                          pkhf2(sm[k4+2][nn], sm[k4+3][nn]));
    size_t tb = ((size_t)((b*8 + (n>>7))*32 + (k0>>5)))*8192;
    uint32_t off = swz64(n & 127, k4 >> 3) + ((k4 >> 2) & 1)*8;
    *(uint2*)((char*)g_XTH + tb + off) = hp;
  }
}

// ===========================================================================
// Pure fp16 GEMM: 256m x 128n per CTA, K=1024, BK=64 bulk-fed, 1 mma pass.
// MODE 0: A=Weff, B=XT. Fused epilogue -> Q (scaled), K, V fp16 tiles.
// MODE 1: A=Wproj, B=OT. by = ny_base + blockIdx.y (batch chunking).
//         Accumulates into final out (+bias).
// ===========================================================================
#define GSTG 49152u
#define GEMM_SMEM 136192u   // max(1024 + 2*GSTG, 1024 + 256*132*4 epilogue T)

template<int MODE>
__global__ __launch_bounds__(256, 1) void gemm_mma(const float* __restrict__ bias,
                                                   float* __restrict__ outp,
                                                   int ny_base){
  extern __shared__ char smem[];
  const uint32_t sb = smem_u32(smem);
  const int tid = threadIdx.x;
  const int wid = tid >> 5, lane = tid & 31;
  const int mt = blockIdx.x;
  const int by = ny_base + blockIdx.y;
  const int b  = by >> 3;
  const int nt = by & 7;
  const int m0 = mt*256, n0 = nt*128;
  const int wm = (wid >> 1) * 64;
  const int wn = (wid & 1) * 64;

  const char* Ahb = (const char*)(MODE==0 ? (void*)g_WeffH : (void*)g_WprojH) + (size_t)mt*32*16384;
  const char* Bhb = (const char*)(MODE==0 ? (void*)g_XTH : (void*)g_OTH) + (size_t)((b*8+nt)*32)*8192;

  if (tid == 0){ MBARRIER_INIT(sb+8, 1); MBARRIER_INIT(sb+16, 1); }
  __syncthreads();

  float acc[4][8][4];
  #pragma unroll
  for (int i=0;i<4;i++)
    #pragma unroll
    for (int j=0;j<8;j++)
      #pragma unroll
      for (int r=0;r<4;r++) acc[i][j][r] = 0.f;

  auto issue = [&](int kt2){
    if (tid == 0){
      int buf = kt2 & 1;
      uint32_t mb = sb + 8 + buf*8;
      MBARRIER_EXPECT_TX(mb, GSTG);
      uint32_t d = sb + 1024 + buf*GSTG;
      BULKCP(d,         Ahb + (size_t)kt2*32768, 32768, mb);
      BULKCP(d+32768,   Bhb + (size_t)kt2*16384, 16384, mb);
    }
  };

  issue(0);
  for (int kt2 = 0; kt2 < 16; kt2++){
    if (kt2 + 1 < 16) issue(kt2+1);
    MBARRIER_WAIT_PARITY(sb + 8 + (kt2&1)*8, (kt2>>1)&1);
    const uint32_t st = sb + 1024 + (kt2&1)*GSTG;

    #pragma unroll
    for (int s = 0; s < 2; s++){
      const uint32_t Ah = st + s*16384;
      const uint32_t Bh = st + 32768 + s*8192;
      #pragma unroll
      for (int ks = 0; ks < 2; ks++){
        uint32_t ah[4][4], bh[8][2];
        #pragma unroll
        for (int mi = 0; mi < 4; mi++){
          uint32_t row = wm + mi*16 + (lane & 15);
          uint32_t c16 = ks*2 + (lane >> 4);
          ldm4(ah[mi], Ah + swz64(row, c16));
        }
        #pragma unroll
        for (int np = 0; np < 4; np++){
          uint32_t row = wn + np*16 + (lane >> 4)*8 + (lane & 7);
          uint32_t c16 = ks*2 + ((lane >> 3) & 1);
          uint32_t r[4];
          ldm4(r, Bh + swz64(row, c16));
          bh[np*2][0]=r[0]; bh[np*2][1]=r[1]; bh[np*2+1][0]=r[2]; bh[np*2+1][1]=r[3];
        }
        #pragma unroll
        for (int mi=0;mi<4;mi++)
          #pragma unroll
          for (int ni=0;ni<8;ni++) mma16816h(acc[mi][ni], ah[mi], bh[ni]);
      }
    }
    __syncthreads();
  }

  if (MODE == 1){
    // final output: out[(b, cch, qc, n)] += acc + bias  (dwconv pre-wrote)
    #pragma unroll
    for (int mi=0;mi<4;mi++)
      #pragma unroll
      for (int half=0; half<2; half++){
        int gm = m0 + wm + mi*16 + (lane >> 2) + half*8;
        float bi = bias[gm];
        int qc = gm >> 8; int cch = gm & 255;
        float* dst = outp + ((size_t)((b*CC + cch)*4 + qc))*NPIX;
        #pragma unroll
        for (int ni=0;ni<8;ni++){
          int nn = n0 + wn + ni*8 + (lane & 3)*2;
          float2 old = *(float2*)&dst[nn];
          float2 v = make_float2(old.x + acc[mi][ni][half*2+0] + bi,
                                 old.y + acc[mi][ni][half*2+1] + bi);
          *(float2*)&dst[nn] = v;
        }
      }
    return;
  }

  // ---- MODE 0 epilogue: region = Q(0) / K(1) / V(2) ----
  const int region = mt % 3;
  const int qc = mt / 3;
  if (region == 2){
    // V: fp16 stores into (d, n) tiles
    #pragma unroll
    for (int mi=0;mi<4;mi++)
      #pragma unroll
      for (int half=0; half<2; half++){
        int gm = m0 + wm + mi*16 + (lane >> 2) + half*8;
        float bi = bias[gm];
        int o = gm - qc*768; int cch = o & 255;
        int ch = (qc << 8) | cch; int hh = ch >> 7; int dd = ch & 127;
        size_t bhbase = ((size_t)(b*HEADS + hh))*16*16384;
        #pragma unroll
        for (int ni=0;ni<8;ni++){
          int nn = n0 + wn + ni*8 + (lane & 3)*2;
          float v0 = acc[mi][ni][half*2+0] + bi;
          float v1 = acc[mi][ni][half*2+1] + bi;
          size_t tb = bhbase + (size_t)(nn>>6)*16384;
          uint32_t off = swz128(dd, (nn&63)>>3) + (nn&7)*2;
          *(uint32_t*)((char*)g_VH + tb + off) = pkhf2(v0, v1);
        }
      }
  } else {
    // Q/K: stage fp32 into smem (scale folded), transpose, emit (n,d) tiles
    float* T = (float*)(smem + 1024);   // 256 x 132 fp32 = 135168 B
    const float scl = (region == 0) ? 0.12751875542484462f  // qscale*log2e
                                    : 1.f;
    #pragma unroll
    for (int mi=0;mi<4;mi++)
      #pragma unroll
      for (int half=0; half<2; half++){
        int gm = m0 + wm + mi*16 + (lane >> 2) + half*8;
        int row = gm - m0;
        float bi = bias[gm];
        #pragma unroll
        for (int ni=0;ni<8;ni++){
          int nn = wn + ni*8 + (lane & 3)*2;
          T[row*132 + nn]     = (acc[mi][ni][half*2+0] + bi)*scl;
          T[row*132 + nn + 1] = (acc[mi][ni][half*2+1] + bi)*scl;
        }
      }
    __syncthreads();

    char* dh = (region == 0) ? (char*)g_QTH : (char*)g_KTH;
    const int nl = tid & 127;
    const int hp = tid >> 7;            // head parity within tile
    const int n = n0 + nl;
    const int head = qc*2 + hp;
    const size_t tb = ((size_t)((b*HEADS + head)*16 + (n>>6)))*16384;
    const uint32_t r6 = n & 63;
    #pragma unroll
    for (int c16 = 0; c16 < 16; c16++){
      float a[8];
      #pragma unroll
      for (int i=0;i<8;i++) a[i] = T[(hp*128 + c16*8 + i)*132 + nl];
      uint4 H;
      H.x = pkhf2(a[0],a[1]); H.y = pkhf2(a[2],a[3]);
      H.z = pkhf2(a[4],a[5]); H.w = pkhf2(a[6],a[7]);
      *(uint4*)(dh + tb + swz256(r6, c16)) = H;
    }
  }
}

// ===========================================================================
// Flash attention, pure fp16. bh = bh_base + blockIdx.y (batch chunking).
// CTA = 128 queries x (b,h), 256 thr, 8 warps x 16 q-rows.
// ===========================================================================
#define ASTG 32768u
#define AT_SMEM (1024u + 2u*ASTG)

__global__ __launch_bounds__(256, 1) void attn_mma(int bh_base){
  extern __shared__ char smem[];
  const uint32_t sb = smem_u32(smem);
  const int tid = threadIdx.x;
  const int wid = tid >> 5, lane = tid & 31;
  const int bh = bh_base + blockIdx.y;
  const int b = bh >> 3, h = bh & 7;
  const int qi = blockIdx.x;           // q block of 128
  const int q0 = qi * 128;

  if (tid == 0){
    MBARRIER_INIT(sb+8, 1); MBARRIER_INIT(sb+16, 1); MBARRIER_INIT(sb+24, 1);
  }
  __syncthreads();

  // ---- Q load: 2 tiles = 32KB into the stage region
  if (tid == 0){
    MBARRIER_EXPECT_TX(sb+24, 32768);
    const char* qh_g = (const char*)g_QTH + ((size_t)bh*16 + qi*2)*16384;
    BULKCP(sb+1024, qh_g, 32768, sb+24);
  }
  MBARRIER_WAIT_PARITY(sb+24, 0);

  uint32_t qfh[8][4];
  {
    uint32_t row = wid*16 + (lane & 15);
    uint32_t base = sb + 1024 + (row >> 6)*16384;
    uint32_t r6 = row & 63;
    #pragma unroll
    for (int kf = 0; kf < 8; kf++){
      uint32_t c16 = kf*2 + (lane >> 4);
      ldm4(qfh[kf], base + swz256(r6, c16));
    }
  }
  __syncthreads();   // Q consumed; stage region reusable

  const char* kh_g = (const char*)g_KTH + (size_t)bh*16*16384;
  const char* vh_g = (const char*)g_VH  + (size_t)bh*16*16384;

  auto issueKV = [&](int kb){
    if (tid == 0){
      int buf = kb & 1;
      uint32_t mb = sb + 8 + buf*8;
      MBARRIER_EXPECT_TX(mb, ASTG);
      uint32_t d = sb + 1024 + buf*ASTG;
      BULKCP(d,         kh_g + (size_t)kb*16384, 16384, mb);
      BULKCP(d+16384,   vh_g + (size_t)kb*16384, 16384, mb);
    }
  };

  float accO[16][4];
  #pragma unroll
  for (int i=0;i<16;i++)
    #pragma unroll
    for (int r=0;r<4;r++) accO[i][r] = 0.f;
  float m0r = -1e30f, m1r = -1e30f, l0 = 0.f, l1 = 0.f;

  issueKV(0);
  for (int kb = 0; kb < 16; kb++){
    if (kb + 1 < 16) issueKV(kb+1);
    MBARRIER_WAIT_PARITY(sb + 8 + (kb&1)*8, (kb>>1)&1);
    const uint32_t st = sb + 1024 + (kb&1)*ASTG;

    // ---- S = Qh Kh^T  (16q x 64k per warp)
    float S[8][4];
    #pragma unroll
    for (int i=0;i<8;i++)
      #pragma unroll
      for (int r=0;r<4;r++) S[i][r] = 0.f;
    #pragma unroll
    for (int kf = 0; kf < 8; kf++){
      #pragma unroll
      for (int np = 0; np < 4; np++){
        uint32_t row = np*16 + (lane >> 4)*8 + (lane & 7);
        uint32_t c16 = kf*2 + ((lane >> 3) & 1);
        uint32_t r[4];
        ldm4(r, st + swz256(row, c16));
        uint32_t b0[2] = {r[0], r[1]}, b1[2] = {r[2], r[3]};
        mma16816h(S[np*2],   qfh[kf], b0);
        mma16816h(S[np*2+1], qfh[kf], b1);
      }
    }

    // ---- online softmax (log2 domain; log2e folded into Q)
    float mx0 = -1e30f, mx1 = -1e30f;
    #pragma unroll
    for (int i=0;i<8;i++){
      mx0 = fmaxf(mx0, fmaxf(S[i][0], S[i][1]));
      mx1 = fmaxf(mx1, fmaxf(S[i][2], S[i][3]));
    }
    mx0 = fmaxf(mx0, __shfl_xor_sync(0xffffffffu, mx0, 1));
    mx0 = fmaxf(mx0, __shfl_xor_sync(0xffffffffu, mx0, 2));
    mx1 = fmaxf(mx1, __shfl_xor_sync(0xffffffffu, mx1, 1));
    mx1 = fmaxf(mx1, __shfl_xor_sync(0xffffffffu, mx1, 2));
    float mn0 = fmaxf(m0r, mx0), mn1 = fmaxf(m1r, mx1);
    float al0 = exp2f(m0r - mn0), al1 = exp2f(m1r - mn1);
    m0r = mn0; m1r = mn1;

    float rs0 = 0.f, rs1 = 0.f;
    uint32_t ph[4][4];
    #pragma unroll
    for (int nf = 0; nf < 8; nf++){
      float p0 = exp2f(S[nf][0] - mn0);
      float p1 = exp2f(S[nf][1] - mn0);
      float p2 = exp2f(S[nf][2] - mn1);
      float p3 = exp2f(S[nf][3] - mn1);
      rs0 += p0 + p1; rs1 += p2 + p3;
      int kf = nf >> 1, pc = (nf & 1)*2;
      ph[kf][pc+0] = pkhf2(p0, p1);
      ph[kf][pc+1] = pkhf2(p2, p3);
    }
    rs0 += __shfl_xor_sync(0xffffffffu, rs0, 1);
    rs0 += __shfl_xor_sync(0xffffffffu, rs0, 2);
    rs1 += __shfl_xor_sync(0xffffffffu, rs1, 1);
    rs1 += __shfl_xor_sync(0xffffffffu, rs1, 2);
    l0 = l0*al0 + rs0; l1 = l1*al1 + rs1;

    #pragma unroll
    for (int i=0;i<16;i++){
      accO[i][0] *= al0; accO[i][1] *= al0;
      accO[i][2] *= al1; accO[i][3] *= al1;
    }

    // ---- accO += Ph Vh  (16q x 128d per warp)
    const uint32_t vb = st + 16384;
    #pragma unroll
    for (int kf = 0; kf < 4; kf++){
      #pragma unroll
      for (int np = 0; np < 8; np++){
        uint32_t row = np*16 + (lane >> 4)*8 + (lane & 7);
        uint32_t c16 = kf*2 + ((lane >> 3) & 1);
        uint32_t r[4];
        ldm4(r, vb + swz128(row, c16));
        uint32_t b0[2] = {r[0], r[1]}, b1[2] = {r[2], r[3]};
        mma16816h(accO[np*2],   ph[kf], b0);
        mma16816h(accO[np*2+1], ph[kf], b1);
      }
    }
    __syncthreads();
  }

  // ---- epilogue: O/l -> fp16 into tiled OT
  float inv0 = 1.f / l0, inv1 = 1.f / l1;
  int na = q0 + wid*16 + (lane >> 2);
  int nb2 = na + 8;
  #pragma unroll
  for (int nf = 0; nf < 16; nf++){
    int ch = h*HD + nf*8 + (lane & 3)*2;
    float v0 = accO[nf][0]*inv0, v1 = accO[nf][1]*inv0;
    float v2 = accO[nf][2]*inv1, v3 = accO[nf][3]*inv1;
    size_t tba = ((size_t)((b*8 + (na>>7))*32 + (ch>>5)))*8192;
    size_t tbb = ((size_t)((b*8 + (nb2>>7))*32 + (ch>>5)))*8192;
    uint32_t ofa = swz64(na & 127, (ch>>3)&3) + (ch&7)*2;
    uint32_t ofb = swz64(nb2 & 127, (ch>>3)&3) + (ch&7)*2;
    *(uint32_t*)((char*)g_OTH + tba + ofa) = pkhf2(v0, v1);
    *(uint32_t*)((char*)g_OTH + tbb + ofb) = pkhf2(v2, v3);
  }
}

// ---------------------------------------------------------------------------
// Quaternion depthwise 3x3. WRITES (=) conv + pe-bias to output; proj GEMM
// accumulates on top. Runs on the side stream.
// ---------------------------------------------------------------------------
__global__ __launch_bounds__(256) void qdwconv_kernel(const float* __restrict__ x,
                                                      const float* __restrict__ w_pe,
                                                      const float* __restrict__ b_pe,
                                                      float* __restrict__ outp){
  __shared__ float xs[4][1024];
  __shared__ float wt[4][4][9];
  const int bid = blockIdx.x;
  const int c = bid & 255, b = bid >> 8;
  const int tid = threadIdx.x;

  #pragma unroll
  for (int p=0;p<4;p++){
    const float* xp = x + ((size_t)((b*CC + c)*4 + p))*NPIX;
    for (int k=tid; k<1024; k+=256) xs[p][k] = xp[k];
  }
  if (tid < 144){
    int qc = tid/36, p = (tid/9)&3, t = tid%9;
    wt[qc][p][t] = c_SGN[qc*4+p] * w_pe[(c_IDX[qc*4+p]*CC + c)*9 + t];
  }
  __syncthreads();

  float bia[4];
  #pragma unroll
  for (int qc=0;qc<4;qc++) bia[qc] = b_pe[qc*CC + c];

  for (int k=tid; k<1024; k+=256){
    int hh = k >> 5, ww = k & 31;
    float acc[4] = {bia[0],bia[1],bia[2],bia[3]};
    #pragma unroll
    for (int p=0;p<4;p++){
      #pragma unroll
      for (int kh=0;kh<3;kh++){
        int h2 = hh + kh - 1;
        if (h2 < 0 || h2 > 31) continue;
        #pragma unroll
        for (int kw=0;kw<3;kw++){
          int w2 = ww + kw - 1;
          if (w2 < 0 || w2 > 31) continue;
          float xv = xs[p][h2*32 + w2];
          #pragma unroll
          for (int qc=0;qc<4;qc++) acc[qc] = fmaf(wt[qc][p][kh*3+kw], xv, acc[qc]);
        }
      }
    }
    #pragma unroll
    for (int qc=0;qc<4;qc++)
      outp[((size_t)((b*CC + c)*4 + qc))*NPIX + k] = acc[qc];
  }
}

// ---------------------------------------------------------------------------
extern "C" void kernel_launch(void* const* d_in, const int* in_sizes, int n_in,
                              void* d_out, int out_size){
  const float* x      = (const float*)d_in[0];
  const float* w_qkv  = (const float*)d_in[1];
  const float* b_qkv  = (const float*)d_in[2];
  const float* w_proj = (const float*)d_in[3];
  const float* b_proj = (const float*)d_in[4];
  const float* w_pe   = (const float*)d_in[5];
  const float* b_pe   = (const float*)d_in[6];
  float* outp = (float*)d_out;

  (void)in_sizes; (void)n_in; (void)out_size;

  static cudaStream_t s2 = nullptr, s3 = nullptr;
  static cudaEvent_t eFork = nullptr, eW = nullptr, eG = nullptr;
  static cudaEvent_t eA[4] = {nullptr, nullptr, nullptr, nullptr};
  if (s2 == nullptr){
    cudaStreamCreateWithFlags(&s2, cudaStreamNonBlocking);
    cudaStreamCreateWithFlags(&s3, cudaStreamNonBlocking);
    cudaEventCreateWithFlags(&eFork, cudaEventDisableTiming);
    cudaEventCreateWithFlags(&eW, cudaEventDisableTiming);
    cudaEventCreateWithFlags(&eG, cudaEventDisableTiming);
    for (int i = 0; i < 4; i++)
      cudaEventCreateWithFlags(&eA[i], cudaEventDisableTiming);
  }

  cudaFuncSetAttribute(gemm_mma<0>, cudaFuncAttributeMaxDynamicSharedMemorySize,
                       GEMM_SMEM);
  cudaFuncSetAttribute(gemm_mma<1>, cudaFuncAttributeMaxDynamicSharedMemorySize,
                       GEMM_SMEM);
  cudaFuncSetAttribute(attn_mma, cudaFuncAttributeMaxDynamicSharedMemorySize,
                       AT_SMEM);

  void *weffH, *wprojH;
  cudaGetSymbolAddress(&weffH, g_WeffH);
  cudaGetSymbolAddress(&wprojH, g_WprojH);

  // ---- fork ----
  cudaEventRecord(eFork, 0);
  cudaStreamWaitEvent(s2, eFork, 0);
  cudaStreamWaitEvent(s3, eFork, 0);

  // s3: QKV weight prep (memory-bound, overlaps x-prep and dwconv)
  prep_w_kernel<<< MQKV*128/256, 256, 0, s3 >>>(w_qkv, (char*)weffH, 1);
  cudaEventRecord(eW, s3);

  // s2: dwconv (pre-writes output) + proj weight prep
  qdwconv_kernel<<< NB*CC, 256, 0, s2 >>>(x, w_pe, b_pe, outp);
  prep_w_kernel<<< DIM*128/256, 256, 0, s2 >>>(w_proj, (char*)wprojH, 0);

  // main: x prep, then monolithic QKV GEMM (waits for Weff)
  prep_xt_kernel<<< dim3(32,32,8), 256 >>>(x);
  cudaStreamWaitEvent(0, eW, 0);
  gemm_mma<0><<< dim3(12,64), 256, GEMM_SMEM >>>(b_qkv, nullptr, 0);
  cudaEventRecord(eG, 0);

  // s2: attention in 4 batch-pair chunks (each implies prior s2 work done)
  cudaStreamWaitEvent(s2, eG, 0);
  for (int cb = 0; cb < 4; cb++){
    attn_mma<<< dim3(8,16), 256, AT_SMEM, s2 >>>(cb*16);
    cudaEventRecord(eA[cb], s2);
  }

  // main: proj GEMM in matching batch-pair chunks, overlapping attention
  for (int cb = 0; cb < 4; cb++){
    cudaStreamWaitEvent(0, eA[cb], 0);
    gemm_mma<1><<< dim3(4,16), 256, GEMM_SMEM >>>(b_proj, outp, cb*16);
  }
}

// round 15
// speedup vs baseline: 1.6308x; 1.6308x over previous
#include <cuda_runtime.h>
#include <cuda_bf16.h>
#include <cuda_fp16.h>
#include <cstdint>
#include <math.h>

#define NB 8
#define CC 256
#define NPIX 1024
#define HEADS 8
#define HD 128
#define MQKV 3072
#define DIM 1024

// Hamilton tables
__constant__ int   c_IDX[16] = {0,1,2,3, 1,0,3,2, 2,3,0,1, 3,2,1,0};
__constant__ float c_SGN[16] = {1.f,-1.f,-1.f,-1.f, 1.f,1.f,1.f,-1.f,
                                1.f,-1.f,1.f,1.f, 1.f,1.f,-1.f,1.f};

// Scratch (device globals). ALL tensor-core operands pre-tiled + pre-swizzled
// (fp16), fetched with single cp.async.bulk copies.
__device__ __half g_WeffH[(size_t)MQKV*DIM];
__device__ __half g_WprojH[(size_t)DIM*DIM];
__device__ __half g_XTH[(size_t)NB*NPIX*DIM];
__device__ __half g_OTH[(size_t)NB*NPIX*DIM];
__device__ __half g_QTH[(size_t)NB*HEADS*NPIX*HD];  // scale*log2e folded
__device__ __half g_KTH[(size_t)NB*HEADS*NPIX*HD];
__device__ __half g_VH[(size_t)NB*HEADS*HD*NPIX];

// ===========================================================================
// Helpers
// ===========================================================================
__device__ __forceinline__ uint32_t smem_u32(const void* p){
  uint32_t a;
  asm("{ .reg .u64 t; cvta.to.shared.u64 t, %1; cvt.u32.u64 %0, t; }"
      : "=r"(a) : "l"(p));
  return a;
}
__device__ __forceinline__ void ldm4(uint32_t r[4], uint32_t addr){
  asm volatile("ldmatrix.sync.aligned.m8n8.x4.shared.b16 {%0,%1,%2,%3}, [%4];"
    : "=r"(r[0]),"=r"(r[1]),"=r"(r[2]),"=r"(r[3]) : "r"(addr));
}
__device__ __forceinline__ void mma16816h(float c[4], const uint32_t a[4],
                                          const uint32_t b[2]){
  asm volatile(
    "mma.sync.aligned.m16n8k16.row.col.f32.f16.f16.f32 "
    "{%0,%1,%2,%3}, {%4,%5,%6,%7}, {%8,%9}, {%0,%1,%2,%3};"
    : "+f"(c[0]),"+f"(c[1]),"+f"(c[2]),"+f"(c[3])
    : "r"(a[0]),"r"(a[1]),"r"(a[2]),"r"(a[3]), "r"(b[0]),"r"(b[1]));
}
__device__ __forceinline__ uint32_t pkhf2(float a, float b){
  __half2 t = __floats2half2_rn(a, b);
  return *(uint32_t*)&t;
}
#define BULKCP(dst, src, bytes, mb) \
  asm volatile("cp.async.bulk.shared::cluster.global.mbarrier::complete_tx::bytes [%0], [%1], %2, [%3];" \
    :: "r"((uint32_t)(dst)), "l"(src), "r"((uint32_t)(bytes)), "r"((uint32_t)(mb)) : "memory")
#define MBARRIER_INIT(mb, c) \
  asm volatile("mbarrier.init.shared.b64 [%0], %1;" :: "r"((uint32_t)(mb)), "r"((uint32_t)(c)) : "memory")
#define MBARRIER_EXPECT_TX(mb, tx) \
  asm volatile("mbarrier.arrive.expect_tx.shared.b64 _, [%0], %1;" :: "r"((uint32_t)(mb)), "r"((uint32_t)(tx)) : "memory")
#define MBARRIER_WAIT_PARITY(mb, ph) do { \
    uint32_t _m = (uint32_t)(mb); uint32_t _p = (uint32_t)(ph); uint32_t _d; \
    asm volatile("{\n\t.reg .pred p;\n\t" \
        "mbarrier.try_wait.parity.acquire.cta.shared::cta.b64 p, [%1], %2;\n\t" \
        "selp.b32 %0, 1, 0, p;\n\t}" : "=r"(_d) : "r"(_m), "r"(_p) : "memory"); \
    if (!_d) { \
      asm volatile("{\n\t.reg .pred P1;\n\t" \
        "WL_%=:\n\t" \
        "mbarrier.try_wait.parity.acquire.cta.shared::cta.b64 P1, [%0], %1, 0x989680;\n\t" \
        "@P1 bra.uni WD_%=;\n\t" \
        "bra.uni WL_%=;\n\t" \
        "WD_%=:\n\t}" :: "r"(_m), "r"(_p) : "memory"); \
    } \
  } while(0)

// swizzled byte offsets inside tiles (row-major rows of 64/128/256 bytes)
__device__ __forceinline__ uint32_t swz64 (uint32_t r, uint32_t c16){ return r*64u  + ((c16 ^ ((r>>1)&3u))<<4); }
__device__ __forceinline__ uint32_t swz128(uint32_t r, uint32_t c16){ return r*128u + ((c16 ^ (r&7u))<<4); }
__device__ __forceinline__ uint32_t swz256(uint32_t r, uint32_t c16){ return r*256u + ((c16 ^ (r&7u))<<4); }

// ===========================================================================
// Prep: Hamilton-folded weights -> fp16, tiled+swizzled
// ===========================================================================
__global__ void prep_w_kernel(const float* __restrict__ w,
                              char* __restrict__ outH, int is_qkv){
  int idx = blockIdx.x*256 + threadIdx.x;
  int g = idx >> 7, c = idx & 127;
  int k0 = c*8;
  int qc, o;
  if (is_qkv){ qc = g / 768; o = g - qc*768; } else { qc = g >> 8; o = g & 255; }
  int p = k0 >> 8, cch = k0 & 255;
  float s = c_SGN[qc*4+p];
  const float* src = w + ((size_t)(c_IDX[qc*4+p]*(is_qkv?768:256) + o))*256 + cch;
  float4 v0 = *(const float4*)src;
  float4 v1 = *(const float4*)(src+4);
  size_t base = ((size_t)((g>>8)*32 + (c>>2)))*16384;
  uint32_t off = swz64(g & 255, c & 3);
  uint4 H;
  H.x = pkhf2(v0.x*s, v0.y*s); H.y = pkhf2(v0.z*s, v0.w*s);
  H.z = pkhf2(v1.x*s, v1.y*s); H.w = pkhf2(v1.z*s, v1.w*s);
  *(uint4*)(outH + base + off) = H;
}

// x (b, cch, p, n) fp32 -> XT tiles (b, ntile, kt) fp16
__global__ void prep_xt_kernel(const float* __restrict__ x){
  __shared__ float sm[32][33];
  int b = blockIdx.z, k0 = blockIdx.x*32, n0 = blockIdx.y*32;
  int t = threadIdx.x;
  {
    int kk = t >> 3, n4 = (t & 7) << 2;
    int k = k0 + kk; int p = k >> 8, cch = k & 255;
    float4 v = *(const float4*)&x[((size_t)((b*CC+cch)*4 + p))*NPIX + n0 + n4];
    sm[kk][n4] = v.x; sm[kk][n4+1] = v.y; sm[kk][n4+2] = v.z; sm[kk][n4+3] = v.w;
  }
  __syncthreads();
  {
    int nn = t >> 3, k4 = (t & 7) << 2;
    int n = n0 + nn;
    uint2 hp = make_uint2(pkhf2(sm[k4+0][nn], sm[k4+1][nn]),
                          pkhf2(sm[k4+2][nn], sm[k4+3][nn]));
    size_t tb = ((size_t)((b*8 + (n>>7))*32 + (k0>>5)))*8192;
    uint32_t off = swz64(n & 127, k4 >> 3) + ((k4 >> 2) & 1)*8;
    *(uint2*)((char*)g_XTH + tb + off) = hp;
  }
}

// ===========================================================================
// Pure fp16 GEMM: 256m x 128n per CTA, K=1024, BK=64 bulk-fed, 1 mma pass.
// MODE 0: A=Weff, B=XT. Fused epilogue -> Q (scaled), K, V fp16 tiles.
// MODE 1: A=Wproj, B=OT. Accumulates into final out (+bias).
// ===========================================================================
#define GSTG 49152u
#define GEMM_SMEM 136192u   // max(1024 + 2*GSTG, 1024 + 256*132*4 epilogue T)

template<int MODE>
__global__ __launch_bounds__(256, 1) void gemm_mma(const float* __restrict__ bias,
                                                   float* __restrict__ outp){
  extern __shared__ char smem[];
  const uint32_t sb = smem_u32(smem);
  const int tid = threadIdx.x;
  const int wid = tid >> 5, lane = tid & 31;
  const int mt = blockIdx.x;
  const int b  = blockIdx.y >> 3;
  const int nt = blockIdx.y & 7;
  const int m0 = mt*256, n0 = nt*128;
  const int wm = (wid >> 1) * 64;
  const int wn = (wid & 1) * 64;

  const char* Ahb = (const char*)(MODE==0 ? (void*)g_WeffH : (void*)g_WprojH) + (size_t)mt*32*16384;
  const char* Bhb = (const char*)(MODE==0 ? (void*)g_XTH : (void*)g_OTH) + (size_t)((b*8+nt)*32)*8192;

  if (tid == 0){ MBARRIER_INIT(sb+8, 1); MBARRIER_INIT(sb+16, 1); }
  __syncthreads();

  float acc[4][8][4];
  #pragma unroll
  for (int i=0;i<4;i++)
    #pragma unroll
    for (int j=0;j<8;j++)
      #pragma unroll
      for (int r=0;r<4;r++) acc[i][j][r] = 0.f;

  auto issue = [&](int kt2){
    if (tid == 0){
      int buf = kt2 & 1;
      uint32_t mb = sb + 8 + buf*8;
      MBARRIER_EXPECT_TX(mb, GSTG);
      uint32_t d = sb + 1024 + buf*GSTG;
      BULKCP(d,         Ahb + (size_t)kt2*32768, 32768, mb);
      BULKCP(d+32768,   Bhb + (size_t)kt2*16384, 16384, mb);
    }
  };

  issue(0);
  for (int kt2 = 0; kt2 < 16; kt2++){
    if (kt2 + 1 < 16) issue(kt2+1);
    MBARRIER_WAIT_PARITY(sb + 8 + (kt2&1)*8, (kt2>>1)&1);
    const uint32_t st = sb + 1024 + (kt2&1)*GSTG;

    #pragma unroll
    for (int s = 0; s < 2; s++){
      const uint32_t Ah = st + s*16384;
      const uint32_t Bh = st + 32768 + s*8192;
      #pragma unroll
      for (int ks = 0; ks < 2; ks++){
        uint32_t ah[4][4], bh[8][2];
        #pragma unroll
        for (int mi = 0; mi < 4; mi++){
          uint32_t row = wm + mi*16 + (lane & 15);
          uint32_t c16 = ks*2 + (lane >> 4);
          ldm4(ah[mi], Ah + swz64(row, c16));
        }
        #pragma unroll
        for (int np = 0; np < 4; np++){
          uint32_t row = wn + np*16 + (lane >> 4)*8 + (lane & 7);
          uint32_t c16 = ks*2 + ((lane >> 3) & 1);
          uint32_t r[4];
          ldm4(r, Bh + swz64(row, c16));
          bh[np*2][0]=r[0]; bh[np*2][1]=r[1]; bh[np*2+1][0]=r[2]; bh[np*2+1][1]=r[3];
        }
        #pragma unroll
        for (int mi=0;mi<4;mi++)
          #pragma unroll
          for (int ni=0;ni<8;ni++) mma16816h(acc[mi][ni], ah[mi], bh[ni]);
      }
    }
    __syncthreads();
  }

  if (MODE == 1){
    // final output: out[(b, cch, qc, n)] += acc + bias  (dwconv pre-wrote)
    #pragma unroll
    for (int mi=0;mi<4;mi++)
      #pragma unroll
      for (int half=0; half<2; half++){
        int gm = m0 + wm + mi*16 + (lane >> 2) + half*8;
        float bi = bias[gm];
        int qc = gm >> 8; int cch = gm & 255;
        float* dst = outp + ((size_t)((b*CC + cch)*4 + qc))*NPIX;
        #pragma unroll
        for (int ni=0;ni<8;ni++){
          int nn = n0 + wn + ni*8 + (lane & 3)*2;
          float2 old = *(float2*)&dst[nn];
          float2 v = make_float2(old.x + acc[mi][ni][half*2+0] + bi,
                                 old.y + acc[mi][ni][half*2+1] + bi);
          *(float2*)&dst[nn] = v;
        }
      }
    return;
  }

  // ---- MODE 0 epilogue: region = Q(0) / K(1) / V(2) ----
  const int region = mt % 3;
  const int qc = mt / 3;
  if (region == 2){
    // V: fp16 stores into (d, n) tiles
    #pragma unroll
    for (int mi=0;mi<4;mi++)
      #pragma unroll
      for (int half=0; half<2; half++){
        int gm = m0 + wm + mi*16 + (lane >> 2) + half*8;
        float bi = bias[gm];
        int o = gm - qc*768; int cch = o & 255;
        int ch = (qc << 8) | cch; int hh = ch >> 7; int dd = ch & 127;
        size_t bhbase = ((size_t)(b*HEADS + hh))*16*16384;
        #pragma unroll
        for (int ni=0;ni<8;ni++){
          int nn = n0 + wn + ni*8 + (lane & 3)*2;
          float v0 = acc[mi][ni][half*2+0] + bi;
          float v1 = acc[mi][ni][half*2+1] + bi;
          size_t tb = bhbase + (size_t)(nn>>6)*16384;
          uint32_t off = swz128(dd, (nn&63)>>3) + (nn&7)*2;
          *(uint32_t*)((char*)g_VH + tb + off) = pkhf2(v0, v1);
        }
      }
  } else {
    // Q/K: stage fp32 into smem (scale folded), transpose, emit (n,d) tiles
    float* T = (float*)(smem + 1024);   // 256 x 132 fp32 = 135168 B
    const float scl = (region == 0) ? 0.12751875542484462f  // qscale*log2e
                                    : 1.f;
    #pragma unroll
    for (int mi=0;mi<4;mi++)
      #pragma unroll
      for (int half=0; half<2; half++){
        int gm = m0 + wm + mi*16 + (lane >> 2) + half*8;
        int row = gm - m0;
        float bi = bias[gm];
        #pragma unroll
        for (int ni=0;ni<8;ni++){
          int nn = wn + ni*8 + (lane & 3)*2;
          T[row*132 + nn]     = (acc[mi][ni][half*2+0] + bi)*scl;
          T[row*132 + nn + 1] = (acc[mi][ni][half*2+1] + bi)*scl;
        }
      }
    __syncthreads();

    char* dh = (region == 0) ? (char*)g_QTH : (char*)g_KTH;
    const int nl = tid & 127;
    const int hp = tid >> 7;            // head parity within tile
    const int n = n0 + nl;
    const int head = qc*2 + hp;
    const size_t tb = ((size_t)((b*HEADS + head)*16 + (n>>6)))*16384;
    const uint32_t r6 = n & 63;
    #pragma unroll
    for (int c16 = 0; c16 < 16; c16++){
      float a[8];
      #pragma unroll
      for (int i=0;i<8;i++) a[i] = T[(hp*128 + c16*8 + i)*132 + nl];
      uint4 H;
      H.x = pkhf2(a[0],a[1]); H.y = pkhf2(a[2],a[3]);
      H.z = pkhf2(a[4],a[5]); H.w = pkhf2(a[6],a[7]);
      *(uint4*)(dh + tb + swz256(r6, c16)) = H;
    }
  }
}

// ===========================================================================
// Flash attention, pure fp16. S = Qh*Kh; PV = Ph*Vh.
// CTA = (b,h) x 128 queries, 256 thr, 8 warps x 16 q-rows.
// ===========================================================================
#define ASTG 32768u
#define AT_SMEM (1024u + 2u*ASTG)

__global__ __launch_bounds__(256, 1) void attn_mma(){
  extern __shared__ char smem[];
  const uint32_t sb = smem_u32(smem);
  const int tid = threadIdx.x;
  const int wid = tid >> 5, lane = tid & 31;
  const int bh = blockIdx.y;
  const int qi = blockIdx.x;           // q block of 128
  const int q0 = qi * 128;
  const int b = bh >> 3, h = bh & 7;

  if (tid == 0){
    MBARRIER_INIT(sb+8, 1); MBARRIER_INIT(sb+16, 1); MBARRIER_INIT(sb+24, 1);
  }
  __syncthreads();

  // ---- Q load: 2 tiles = 32KB into the stage region
  if (tid == 0){
    MBARRIER_EXPECT_TX(sb+24, 32768);
    const char* qh_g = (const char*)g_QTH + ((size_t)bh*16 + qi*2)*16384;
    BULKCP(sb+1024, qh_g, 32768, sb+24);
  }
  MBARRIER_WAIT_PARITY(sb+24, 0);

  uint32_t qfh[8][4];
  {
    uint32_t row = wid*16 + (lane & 15);
    uint32_t base = sb + 1024 + (row >> 6)*16384;
    uint32_t r6 = row & 63;
    #pragma unroll
    for (int kf = 0; kf < 8; kf++){
      uint32_t c16 = kf*2 + (lane >> 4);
      ldm4(qfh[kf], base + swz256(r6, c16));
    }
  }
  __syncthreads();   // Q consumed; stage region reusable

  const char* kh_g = (const char*)g_KTH + (size_t)bh*16*16384;
  const char* vh_g = (const char*)g_VH  + (size_t)bh*16*16384;

  auto issueKV = [&](int kb){
    if (tid == 0){
      int buf = kb & 1;
      uint32_t mb = sb + 8 + buf*8;
      MBARRIER_EXPECT_TX(mb, ASTG);
      uint32_t d = sb + 1024 + buf*ASTG;
      BULKCP(d,         kh_g + (size_t)kb*16384, 16384, mb);
      BULKCP(d+16384,   vh_g + (size_t)kb*16384, 16384, mb);
    }
  };

  float accO[16][4];
  #pragma unroll
  for (int i=0;i<16;i++)
    #pragma unroll
    for (int r=0;r<4;r++) accO[i][r] = 0.f;
  float m0r = -1e30f, m1r = -1e30f, l0 = 0.f, l1 = 0.f;

  issueKV(0);
  for (int kb = 0; kb < 16; kb++){
    if (kb + 1 < 16) issueKV(kb+1);
    MBARRIER_WAIT_PARITY(sb + 8 + (kb&1)*8, (kb>>1)&1);
    const uint32_t st = sb + 1024 + (kb&1)*ASTG;

    // ---- S = Qh Kh^T  (16q x 64k per warp)
    float S[8][4];
    #pragma unroll
    for (int i=0;i<8;i++)
      #pragma unroll
      for (int r=0;r<4;r++) S[i][r] = 0.f;
    #pragma unroll
    for (int kf = 0; kf < 8; kf++){
      #pragma unroll
      for (int np = 0; np < 4; np++){
        uint32_t row = np*16 + (lane >> 4)*8 + (lane & 7);
        uint32_t c16 = kf*2 + ((lane >> 3) & 1);
        uint32_t r[4];
        ldm4(r, st + swz256(row, c16));
        uint32_t b0[2] = {r[0], r[1]}, b1[2] = {r[2], r[3]};
        mma16816h(S[np*2],   qfh[kf], b0);
        mma16816h(S[np*2+1], qfh[kf], b1);
      }
    }

    // ---- online softmax (log2 domain; log2e folded into Q)
    float mx0 = -1e30f, mx1 = -1e30f;
    #pragma unroll
    for (int i=0;i<8;i++){
      mx0 = fmaxf(mx0, fmaxf(S[i][0], S[i][1]));
      mx1 = fmaxf(mx1, fmaxf(S[i][2], S[i][3]));
    }
    mx0 = fmaxf(mx0, __shfl_xor_sync(0xffffffffu, mx0, 1));
    mx0 = fmaxf(mx0, __shfl_xor_sync(0xffffffffu, mx0, 2));
    mx1 = fmaxf(mx1, __shfl_xor_sync(0xffffffffu, mx1, 1));
    mx1 = fmaxf(mx1, __shfl_xor_sync(0xffffffffu, mx1, 2));
    float mn0 = fmaxf(m0r, mx0), mn1 = fmaxf(m1r, mx1);
    float al0 = exp2f(m0r - mn0), al1 = exp2f(m1r - mn1);
    m0r = mn0; m1r = mn1;

    float rs0 = 0.f, rs1 = 0.f;
    uint32_t ph[4][4];
    #pragma unroll
    for (int nf = 0; nf < 8; nf++){
      float p0 = exp2f(S[nf][0] - mn0);
      float p1 = exp2f(S[nf][1] - mn0);
      float p2 = exp2f(S[nf][2] - mn1);
      float p3 = exp2f(S[nf][3] - mn1);
      rs0 += p0 + p1; rs1 += p2 + p3;
      int kf = nf >> 1, pc = (nf & 1)*2;
      ph[kf][pc+0] = pkhf2(p0, p1);
      ph[kf][pc+1] = pkhf2(p2, p3);
    }
    rs0 += __shfl_xor_sync(0xffffffffu, rs0, 1);
    rs0 += __shfl_xor_sync(0xffffffffu, rs0, 2);
    rs1 += __shfl_xor_sync(0xffffffffu, rs1, 1);
    rs1 += __shfl_xor_sync(0xffffffffu, rs1, 2);
    l0 = l0*al0 + rs0; l1 = l1*al1 + rs1;

    #pragma unroll
    for (int i=0;i<16;i++){
      accO[i][0] *= al0; accO[i][1] *= al0;
      accO[i][2] *= al1; accO[i][3] *= al1;
    }

    // ---- accO += Ph Vh  (16q x 128d per warp)
    const uint32_t vb = st + 16384;
    #pragma unroll
    for (int kf = 0; kf < 4; kf++){
      #pragma unroll
      for (int np = 0; np < 8; np++){
        uint32_t row = np*16 + (lane >> 4)*8 + (lane & 7);
        uint32_t c16 = kf*2 + ((lane >> 3) & 1);
        uint32_t r[4];
        ldm4(r, vb + swz128(row, c16));
        uint32_t b0[2] = {r[0], r[1]}, b1[2] = {r[2], r[3]};
        mma16816h(accO[np*2],   ph[kf], b0);
        mma16816h(accO[np*2+1], ph[kf], b1);
      }
    }
    __syncthreads();
  }

  // ---- epilogue: O/l -> fp16 into tiled OT
  float inv0 = 1.f / l0, inv1 = 1.f / l1;
  int na = q0 + wid*16 + (lane >> 2);
  int nb2 = na + 8;
  #pragma unroll
  for (int nf = 0; nf < 16; nf++){
    int ch = h*HD + nf*8 + (lane & 3)*2;
    float v0 = accO[nf][0]*inv0, v1 = accO[nf][1]*inv0;
    float v2 = accO[nf][2]*inv1, v3 = accO[nf][3]*inv1;
    size_t tba = ((size_t)((b*8 + (na>>7))*32 + (ch>>5)))*8192;
    size_t tbb = ((size_t)((b*8 + (nb2>>7))*32 + (ch>>5)))*8192;
    uint32_t ofa = swz64(na & 127, (ch>>3)&3) + (ch&7)*2;
    uint32_t ofb = swz64(nb2 & 127, (ch>>3)&3) + (ch&7)*2;
    *(uint32_t*)((char*)g_OTH + tba + ofa) = pkhf2(v0, v1);
    *(uint32_t*)((char*)g_OTH + tbb + ofb) = pkhf2(v2, v3);
  }
}

// ---------------------------------------------------------------------------
// Quaternion depthwise 3x3. WRITES (=) conv + pe-bias to output; proj GEMM
// accumulates on top. Runs on the side stream.
// ---------------------------------------------------------------------------
__global__ __launch_bounds__(256) void qdwconv_kernel(const float* __restrict__ x,
                                                      const float* __restrict__ w_pe,
                                                      const float* __restrict__ b_pe,
                                                      float* __restrict__ outp){
  __shared__ float xs[4][1024];
  __shared__ float wt[4][4][9];
  const int bid = blockIdx.x;
  const int c = bid & 255, b = bid >> 8;
  const int tid = threadIdx.x;

  #pragma unroll
  for (int p=0;p<4;p++){
    const float* xp = x + ((size_t)((b*CC + c)*4 + p))*NPIX;
    for (int k=tid; k<1024; k+=256) xs[p][k] = xp[k];
  }
  if (tid < 144){
    int qc = tid/36, p = (tid/9)&3, t = tid%9;
    wt[qc][p][t] = c_SGN[qc*4+p] * w_pe[(c_IDX[qc*4+p]*CC + c)*9 + t];
  }
  __syncthreads();

  float bia[4];
  #pragma unroll
  for (int qc=0;qc<4;qc++) bia[qc] = b_pe[qc*CC + c];

  for (int k=tid; k<1024; k+=256){
    int hh = k >> 5, ww = k & 31;
    float acc[4] = {bia[0],bia[1],bia[2],bia[3]};
    #pragma unroll
    for (int p=0;p<4;p++){
      #pragma unroll
      for (int kh=0;kh<3;kh++){
        int h2 = hh + kh - 1;
        if (h2 < 0 || h2 > 31) continue;
        #pragma unroll
        for (int kw=0;kw<3;kw++){
          int w2 = ww + kw - 1;
          if (w2 < 0 || w2 > 31) continue;
          float xv = xs[p][h2*32 + w2];
          #pragma unroll
          for (int qc=0;qc<4;qc++) acc[qc] = fmaf(wt[qc][p][kh*3+kw], xv, acc[qc]);
        }
      }
    }
    #pragma unroll
    for (int qc=0;qc<4;qc++)
      outp[((size_t)((b*CC + c)*4 + qc))*NPIX + k] = acc[qc];
  }
}

// ---------------------------------------------------------------------------
extern "C" void kernel_launch(void* const* d_in, const int* in_sizes, int n_in,
                              void* d_out, int out_size){
  const float* x      = (const float*)d_in[0];
  const float* w_qkv  = (const float*)d_in[1];
  const float* b_qkv  = (const float*)d_in[2];
  const float* w_proj = (const float*)d_in[3];
  const float* b_proj = (const float*)d_in[4];
  const float* w_pe   = (const float*)d_in[5];
  const float* b_pe   = (const float*)d_in[6];
  float* outp = (float*)d_out;

  (void)in_sizes; (void)n_in; (void)out_size;

  static cudaStream_t s2 = nullptr, s3 = nullptr;
  static cudaEvent_t eFork = nullptr, eW = nullptr, eJoin = nullptr;
  if (s2 == nullptr){
    cudaStreamCreateWithFlags(&s2, cudaStreamNonBlocking);
    cudaStreamCreateWithFlags(&s3, cudaStreamNonBlocking);
    cudaEventCreateWithFlags(&eFork, cudaEventDisableTiming);
    cudaEventCreateWithFlags(&eW, cudaEventDisableTiming);
    cudaEventCreateWithFlags(&eJoin, cudaEventDisableTiming);
  }

  cudaFuncSetAttribute(gemm_mma<0>, cudaFuncAttributeMaxDynamicSharedMemorySize,
                       GEMM_SMEM);
  cudaFuncSetAttribute(gemm_mma<1>, cudaFuncAttributeMaxDynamicSharedMemorySize,
                       GEMM_SMEM);
  cudaFuncSetAttribute(attn_mma, cudaFuncAttributeMaxDynamicSharedMemorySize,
                       AT_SMEM);

  void *weffH, *wprojH;
  cudaGetSymbolAddress(&weffH, g_WeffH);
  cudaGetSymbolAddress(&wprojH, g_WprojH);

  // ---- fork ----
  cudaEventRecord(eFork, 0);
  cudaStreamWaitEvent(s2, eFork, 0);
  cudaStreamWaitEvent(s3, eFork, 0);

  // s3: QKV weight prep (memory-bound; overlaps prep_xt + dwconv)
  prep_w_kernel<<< MQKV*128/256, 256, 0, s3 >>>(w_qkv, (char*)weffH, 1);
  cudaEventRecord(eW, s3);

  // s2: dwconv (pre-writes output) then proj weight prep; both hidden
  qdwconv_kernel<<< NB*CC, 256, 0, s2 >>>(x, w_pe, b_pe, outp);
  prep_w_kernel<<< DIM*128/256, 256, 0, s2 >>>(w_proj, (char*)wprojH, 0);
  cudaEventRecord(eJoin, s2);

  // main: x prep, then monolithic QKV GEMM (after Weff ready)
  prep_xt_kernel<<< dim3(32,32,8), 256 >>>(x);
  cudaStreamWaitEvent(0, eW, 0);
  gemm_mma<0><<< dim3(12,64), 256, GEMM_SMEM >>>(b_qkv, nullptr);

  // Attention: monolithic, 8 q-tiles x 64 (b,h)
  attn_mma<<< dim3(8,64), 256, AT_SMEM >>>();

  // ---- join: dwconv output + Wproj ready before proj accumulates ----
  cudaStreamWaitEvent(0, eJoin, 0);

  // Proj: (1024 x 8192) fp16 -> accumulate into final output
  gemm_mma<1><<< dim3(4,64), 256, GEMM_SMEM >>>(b_proj, outp);
}